// round 5
// baseline (speedup 1.0000x reference)
#include <cuda_runtime.h>
#include <cuda_bf16.h>
#include <math.h>

// ---------------------------------------------------------------------------
// GCN forward, restructured + bf16 gather payloads:
//   xb = bf16(x)
//   [fused] t1 = A xb (smem)  ->  h = elu(t1 @ W1 + b1) stored bf16
//   pooled_g += (A h)_i   (fused agg2 + mean-pool, smem staging)
//   pooled_mean @ W2 -> concat stats -> MLP -> log_softmax
// All accumulation fp32; bf16 only on the gathered payloads (x rows, h rows).
// Integer inputs (edge_index, batch) arrive as int32.
// ---------------------------------------------------------------------------

#define MAXN 100000
#define MAXE 1600000
#define MAXG 64
#define MAXB ((MAXN + 4095) / 4096)

__device__ int   g_indeg[MAXN];
__device__ int   g_rowptr[MAXN + 1];
__device__ int   g_cursor[MAXN];
__device__ int   g_col[MAXE];
__device__ int   g_bsum[MAXB + 1];
__device__ int   g_cnti[MAXG];
__device__ float g_dinv[MAXN];
__device__ __align__(16) __nv_bfloat16 g_xb[(size_t)MAXN * 64];
__device__ __align__(16) __nv_bfloat16 g_hb[(size_t)MAXN * 128];
__device__ float g_pooled[MAXG * 128];

// ---------------- init: zero scratch (runs every replay) ---------------------
__global__ void init_kernel(int n, int g) {
    int i = blockIdx.x * blockDim.x + threadIdx.x;
    if (i < n) g_indeg[i] = 0;
    if (i < g * 128) g_pooled[i] = 0.0f;
    if (i < g) g_cnti[i] = 0;
}

// ------------- convert x -> bf16 (float4 granularity) + count degrees --------
__global__ void convert_count_kernel(const float* __restrict__ x,
                                     const int* __restrict__ ei,
                                     int nconv, int e) {
    int idx = blockIdx.x * blockDim.x + threadIdx.x;
    if (idx < nconv) {
        float4 v = ((const float4*)x)[idx];
        __nv_bfloat162 lo = __floats2bfloat162_rn(v.x, v.y);
        __nv_bfloat162 hi = __floats2bfloat162_rn(v.z, v.w);
        uint2 packed;
        packed.x = *reinterpret_cast<unsigned int*>(&lo);
        packed.y = *reinterpret_cast<unsigned int*>(&hi);
        ((uint2*)g_xb)[idx] = packed;
    }
    if (idx < e) atomicAdd(&g_indeg[ei[e + idx]], 1);
}

// ---------------- scan phase 1: per-block (4096 elems) exclusive scan --------
__global__ void __launch_bounds__(256) scan1_kernel(int n) {
    __shared__ int sh[4096];
    __shared__ int wsum[8];
    int t = threadIdx.x;
    int base = blockIdx.x * 4096;
#pragma unroll
    for (int j = 0; j < 16; j++) {
        int idx = base + t + j * 256;
        sh[t + j * 256] = (idx < n) ? g_indeg[idx] : 0;
    }
    __syncthreads();
    int v[16];
    int run = 0;
#pragma unroll
    for (int j = 0; j < 16; j++) { v[j] = run; run += sh[t * 16 + j]; }
    int lane = t & 31, w = t >> 5;
    int incl = run;
#pragma unroll
    for (int off = 1; off < 32; off <<= 1) {
        int tmp = __shfl_up_sync(0xffffffffu, incl, off);
        if (lane >= off) incl += tmp;
    }
    if (lane == 31) wsum[w] = incl;
    __syncthreads();
    if (t == 0) {
        int s = 0;
#pragma unroll
        for (int k = 0; k < 8; k++) { int x2 = wsum[k]; wsum[k] = s; s += x2; }
        g_bsum[blockIdx.x] = s;
    }
    __syncthreads();
    int texcl = wsum[w] + incl - run;
#pragma unroll
    for (int j = 0; j < 16; j++) sh[t * 16 + j] = texcl + v[j];
    __syncthreads();
#pragma unroll
    for (int j = 0; j < 16; j++) {
        int idx = base + t + j * 256;
        if (idx < n) g_rowptr[idx] = sh[t + j * 256];
    }
}

// ---------------- scan phase 2: scan block sums (1 warp) ----------------------
__global__ void scan2_kernel(int nb, int n) {
    int lane = threadIdx.x;
    int carry = 0;
    for (int base = 0; base < nb; base += 32) {
        int idx = base + lane;
        int x = (idx < nb) ? g_bsum[idx] : 0;
        int incl = x;
#pragma unroll
        for (int off = 1; off < 32; off <<= 1) {
            int tmp = __shfl_up_sync(0xffffffffu, incl, off);
            if (lane >= off) incl += tmp;
        }
        int excl = carry + incl - x;
        if (idx < nb) g_bsum[idx] = excl;
        carry += __shfl_sync(0xffffffffu, incl, 31);
    }
    if (lane == 0) g_rowptr[n] = carry;
}

// -------- scan phase 3: add block offsets + dinv + cursor + graph counts ------
__global__ void scan3_kernel(const int* __restrict__ batch, int n) {
    int i = blockIdx.x * blockDim.x + threadIdx.x;
    if (i < n) {
        int r = g_rowptr[i] + g_bsum[i >> 12];
        g_rowptr[i] = r;
        g_cursor[i] = r;
        g_dinv[i] = rsqrtf((float)(g_indeg[i] + 1));
        atomicAdd(&g_cnti[batch[i]], 1);
    }
}

// ---------------- scatter edges into CSR --------------------------------------
__global__ void scatter_kernel(const int* __restrict__ ei, int e) {
    int idx = blockIdx.x * blockDim.x + threadIdx.x;
    if (idx < e) {
        int s = ei[idx];
        int d = ei[e + idx];
        int pos = atomicAdd(&g_cursor[d], 1);
        g_col[pos] = s;
    }
}

// ------- fused agg1 + GEMM1: block = 64 nodes ---------------------------------
// Phase A: warp w aggregates nodes [base+w*8, base+w*8+8) of A·xb into As (fp32)
// Phase B: h = elu(As @ W1 + b1) with packed f32x2 FFMA, stored bf16 to g_hb
__global__ void __launch_bounds__(256) agg1_gemm1_kernel(const float* __restrict__ W1,
                                                         const float* __restrict__ b1,
                                                         int n) {
    __shared__ float As[64 * 64];
    __shared__ float Ws[64 * 128];
    int tid = threadIdx.x;
    int lane = tid & 31;
    int w = tid >> 5;
    int base = blockIdx.x * 64;

    const float4* Wv = (const float4*)W1;
    float4* Wsv = (float4*)Ws;
#pragma unroll
    for (int i = 0; i < 8; i++) Wsv[tid + i * 256] = Wv[tid + i * 256];

    // Phase A: aggregation, 8 nodes per warp
#pragma unroll 1
    for (int j = 0; j < 8; j++) {
        int nl = w * 8 + j;            // node local 0..63
        int i = base + nl;
        float2 acc = make_float2(0.f, 0.f);
        if (i < n) {
            int p0 = g_rowptr[i], p1 = g_rowptr[i + 1];
            int p = p0;
            for (; p + 4 <= p1; p += 4) {
                int s0 = g_col[p], s1 = g_col[p + 1], s2 = g_col[p + 2], s3 = g_col[p + 3];
                float w0 = g_dinv[s0], w1 = g_dinv[s1], w2 = g_dinv[s2], w3 = g_dinv[s3];
                float2 v0 = __bfloat1622float2(*(const __nv_bfloat162*)(g_xb + (size_t)s0 * 64 + lane * 2));
                float2 v1 = __bfloat1622float2(*(const __nv_bfloat162*)(g_xb + (size_t)s1 * 64 + lane * 2));
                float2 v2 = __bfloat1622float2(*(const __nv_bfloat162*)(g_xb + (size_t)s2 * 64 + lane * 2));
                float2 v3 = __bfloat1622float2(*(const __nv_bfloat162*)(g_xb + (size_t)s3 * 64 + lane * 2));
                acc.x = fmaf(w0, v0.x, acc.x); acc.y = fmaf(w0, v0.y, acc.y);
                acc.x = fmaf(w1, v1.x, acc.x); acc.y = fmaf(w1, v1.y, acc.y);
                acc.x = fmaf(w2, v2.x, acc.x); acc.y = fmaf(w2, v2.y, acc.y);
                acc.x = fmaf(w3, v3.x, acc.x); acc.y = fmaf(w3, v3.y, acc.y);
            }
            for (; p < p1; ++p) {
                int s = g_col[p];
                float ws = g_dinv[s];
                float2 v = __bfloat1622float2(*(const __nv_bfloat162*)(g_xb + (size_t)s * 64 + lane * 2));
                acc.x = fmaf(ws, v.x, acc.x); acc.y = fmaf(ws, v.y, acc.y);
            }
            float di = g_dinv[i];
            float2 xi = __bfloat1622float2(*(const __nv_bfloat162*)(g_xb + (size_t)i * 64 + lane * 2));
            acc.x = di * acc.x + di * di * xi.x;
            acc.y = di * acc.y + di * di * xi.y;
        }
        *(float2*)(As + nl * 64 + lane * 2) = acc;
    }
    __syncthreads();

    // Phase B: GEMM with packed f32x2
    int tx = tid & 31, ty = tid >> 5;
    int c0 = tx * 4, r0 = ty * 8;
    unsigned long long accp[8][2];
#pragma unroll
    for (int r = 0; r < 8; r++) { accp[r][0] = 0ull; accp[r][1] = 0ull; }

#pragma unroll 4
    for (int k = 0; k < 64; k++) {
        ulonglong2 bb = *(const ulonglong2*)(Ws + k * 128 + c0);
#pragma unroll
        for (int r = 0; r < 8; r++) {
            unsigned int au = __float_as_uint(As[(r0 + r) * 64 + k]);
            unsigned long long ap;
            asm("mov.b64 %0, {%1, %1};" : "=l"(ap) : "r"(au));
            asm("fma.rn.f32x2 %0, %1, %2, %0;" : "+l"(accp[r][0]) : "l"(ap), "l"(bb.x));
            asm("fma.rn.f32x2 %0, %1, %2, %0;" : "+l"(accp[r][1]) : "l"(ap), "l"(bb.y));
        }
    }

    float4 bias = *(const float4*)&b1[c0];
#pragma unroll
    for (int r = 0; r < 8; r++) {
        int row = base + r0 + r;
        if (row < n) {
            unsigned int u0, u1, u2, u3;
            asm("mov.b64 {%0, %1}, %2;" : "=r"(u0), "=r"(u1) : "l"(accp[r][0]));
            asm("mov.b64 {%0, %1}, %2;" : "=r"(u2), "=r"(u3) : "l"(accp[r][1]));
            float4 o;
            o.x = __uint_as_float(u0) + bias.x;
            o.y = __uint_as_float(u1) + bias.y;
            o.z = __uint_as_float(u2) + bias.z;
            o.w = __uint_as_float(u3) + bias.w;
            o.x = (o.x > 0.f) ? o.x : expm1f(o.x);
            o.y = (o.y > 0.f) ? o.y : expm1f(o.y);
            o.z = (o.z > 0.f) ? o.z : expm1f(o.z);
            o.w = (o.w > 0.f) ? o.w : expm1f(o.w);
            __nv_bfloat162 lo = __floats2bfloat162_rn(o.x, o.y);
            __nv_bfloat162 hi = __floats2bfloat162_rn(o.z, o.w);
            uint2 packed;
            packed.x = *reinterpret_cast<unsigned int*>(&lo);
            packed.y = *reinterpret_cast<unsigned int*>(&hi);
            *(uint2*)(g_hb + (size_t)row * 128 + c0) = packed;
        }
    }
}

// -------- agg2 + mean-pool: pooled[g] += (A h)_i, bf16 gathers ----------------
__device__ __forceinline__ float4 ld_h4(const __nv_bfloat16* p) {
    uint2 raw = *(const uint2*)p;
    __nv_bfloat162 b0 = *reinterpret_cast<__nv_bfloat162*>(&raw.x);
    __nv_bfloat162 b1 = *reinterpret_cast<__nv_bfloat162*>(&raw.y);
    float2 f0 = __bfloat1622float2(b0);
    float2 f1 = __bfloat1622float2(b1);
    return make_float4(f0.x, f0.y, f1.x, f1.y);
}

__global__ void __launch_bounds__(256) agg2_pool_kernel(const int* __restrict__ batch, int n) {
    __shared__ float ps[128];
    __shared__ int g0_s;
    int tid = threadIdx.x;
    int lane = tid & 31;
    int wid = tid >> 5;
    int node0 = blockIdx.x * 8;
    if (tid < 128) ps[tid] = 0.0f;
    if (tid == 0) g0_s = batch[node0 < n ? node0 : (n - 1)];
    __syncthreads();
    int g0 = g0_s;

    int i = node0 + wid;
    if (i < n) {
        int p0 = g_rowptr[i], p1 = g_rowptr[i + 1];
        float4 acc = make_float4(0.f, 0.f, 0.f, 0.f);
        int p = p0;
        for (; p + 4 <= p1; p += 4) {
            int s0 = g_col[p], s1 = g_col[p + 1], s2 = g_col[p + 2], s3 = g_col[p + 3];
            float w0 = g_dinv[s0], w1 = g_dinv[s1], w2 = g_dinv[s2], w3 = g_dinv[s3];
            float4 v0 = ld_h4(g_hb + (size_t)s0 * 128 + lane * 4);
            float4 v1 = ld_h4(g_hb + (size_t)s1 * 128 + lane * 4);
            float4 v2 = ld_h4(g_hb + (size_t)s2 * 128 + lane * 4);
            float4 v3 = ld_h4(g_hb + (size_t)s3 * 128 + lane * 4);
            acc.x = fmaf(w0, v0.x, acc.x); acc.y = fmaf(w0, v0.y, acc.y);
            acc.z = fmaf(w0, v0.z, acc.z); acc.w = fmaf(w0, v0.w, acc.w);
            acc.x = fmaf(w1, v1.x, acc.x); acc.y = fmaf(w1, v1.y, acc.y);
            acc.z = fmaf(w1, v1.z, acc.z); acc.w = fmaf(w1, v1.w, acc.w);
            acc.x = fmaf(w2, v2.x, acc.x); acc.y = fmaf(w2, v2.y, acc.y);
            acc.z = fmaf(w2, v2.z, acc.z); acc.w = fmaf(w2, v2.w, acc.w);
            acc.x = fmaf(w3, v3.x, acc.x); acc.y = fmaf(w3, v3.y, acc.y);
            acc.z = fmaf(w3, v3.z, acc.z); acc.w = fmaf(w3, v3.w, acc.w);
        }
        for (; p < p1; ++p) {
            int s = g_col[p];
            float w = g_dinv[s];
            float4 v = ld_h4(g_hb + (size_t)s * 128 + lane * 4);
            acc.x = fmaf(w, v.x, acc.x); acc.y = fmaf(w, v.y, acc.y);
            acc.z = fmaf(w, v.z, acc.z); acc.w = fmaf(w, v.w, acc.w);
        }
        float di = g_dinv[i];
        float4 hi = ld_h4(g_hb + (size_t)i * 128 + lane * 4);
        float4 r;
        r.x = di * acc.x + di * di * hi.x;
        r.y = di * acc.y + di * di * hi.y;
        r.z = di * acc.z + di * di * hi.z;
        r.w = di * acc.w + di * di * hi.w;
        int g = batch[i];
        if (g == g0) {
            atomicAdd(&ps[lane * 4 + 0], r.x);
            atomicAdd(&ps[lane * 4 + 1], r.y);
            atomicAdd(&ps[lane * 4 + 2], r.z);
            atomicAdd(&ps[lane * 4 + 3], r.w);
        } else {
            float* pg = g_pooled + g * 128 + lane * 4;
            atomicAdd(pg + 0, r.x);
            atomicAdd(pg + 1, r.y);
            atomicAdd(pg + 2, r.z);
            atomicAdd(pg + 3, r.w);
        }
    }
    __syncthreads();
    if (tid < 128) atomicAdd(&g_pooled[g0 * 128 + tid], ps[tid]);
}

// ---------------- epilogue: W2 + MLP + log_softmax (1 block per graph) --------
__global__ void __launch_bounds__(128) final_kernel(
    const float* __restrict__ stats,
    const float* __restrict__ W2, const float* __restrict__ b2,
    const float* __restrict__ Wf1, const float* __restrict__ bf1,
    const float* __restrict__ Wf2, const float* __restrict__ bf2,
    float* __restrict__ out) {
    __shared__ float pm[128];
    __shared__ float zin[138];
    __shared__ float z1[20];
    __shared__ float z2[5];
    int g = blockIdx.x, t = threadIdx.x;
    float c = fmaxf((float)g_cnti[g], 1.0f);
    pm[t] = g_pooled[g * 128 + t] / c;
    __syncthreads();
    float acc = b2[t];
#pragma unroll 8
    for (int k = 0; k < 128; k++) acc = fmaf(pm[k], W2[k * 128 + t], acc);
    zin[t] = acc;
    if (t < 10) zin[128 + t] = stats[g * 10 + t];
    __syncthreads();
    if (t < 20) {
        float a = bf1[t];
        for (int k = 0; k < 138; k++) a = fmaf(zin[k], Wf1[k * 20 + t], a);
        z1[t] = fmaxf(a, 0.0f);
    }
    __syncthreads();
    if (t < 5) {
        float a = bf2[t];
        for (int k = 0; k < 20; k++) a = fmaf(z1[k], Wf2[k * 5 + t], a);
        z2[t] = a;
    }
    __syncthreads();
    if (t == 0) {
        float m = z2[0];
        for (int i = 1; i < 5; i++) m = fmaxf(m, z2[i]);
        float sum = 0.0f;
        for (int i = 0; i < 5; i++) sum += expf(z2[i] - m);
        float ls = m + logf(sum);
        for (int i = 0; i < 5; i++) out[g * 5 + i] = z2[i] - ls;
    }
}

// ---------------------------------------------------------------------------
extern "C" void kernel_launch(void* const* d_in, const int* in_sizes, int n_in,
                              void* d_out, int out_size) {
    const float* x     = (const float*)d_in[0];
    const int*   ei    = (const int*)d_in[1];
    const int*   batch = (const int*)d_in[2];
    const float* stats = (const float*)d_in[4];
    const float* W1    = (const float*)d_in[5];
    const float* b1    = (const float*)d_in[6];
    const float* W2    = (const float*)d_in[7];
    const float* b2    = (const float*)d_in[8];
    const float* Wf1   = (const float*)d_in[9];
    const float* bf1   = (const float*)d_in[10];
    const float* Wf2   = (const float*)d_in[11];
    const float* bf2   = (const float*)d_in[12];

    int n = in_sizes[0] / 64;
    int e = in_sizes[1] / 2;
    int G = in_sizes[4] / 10;
    int nb = (n + 4095) / 4096;
    int nconv = n * 16;                       // number of float4s in x
    int big = (nconv > e) ? nconv : e;

    init_kernel<<<(n + 255) / 256, 256>>>(n, G);
    convert_count_kernel<<<(big + 255) / 256, 256>>>(x, ei, nconv, e);
    scan1_kernel<<<nb, 256>>>(n);
    scan2_kernel<<<1, 32>>>(nb, n);
    scan3_kernel<<<(n + 255) / 256, 256>>>(batch, n);
    scatter_kernel<<<(e + 255) / 256, 256>>>(ei, e);
    agg1_gemm1_kernel<<<(n + 63) / 64, 256>>>(W1, b1, n);
    agg2_pool_kernel<<<(n + 7) / 8, 256>>>(batch, n);
    final_kernel<<<G, 128>>>(stats, W2, b2, Wf1, bf1, Wf2, bf2, (float*)d_out);
}

// round 6
// speedup vs baseline: 1.1082x; 1.1082x over previous
#include <cuda_runtime.h>
#include <cuda_bf16.h>
#include <math.h>

// ---------------------------------------------------------------------------
// GCN forward:
//   xb = bf16(x); t1 = A xb (warp-per-node); h = elu(t1@W1+b1) -> bf16
//   pooled_g += (A h)_i (warp-per-node, smem staging); tiny MLP epilogue.
// Accumulation fp32; bf16 only on gathered payloads. int inputs are int32.
// ---------------------------------------------------------------------------

#define MAXN 100000
#define MAXE 1600000
#define MAXG 64
#define MAXB ((MAXN + 4095) / 4096)

__device__ int   g_indeg[MAXN];
__device__ int   g_rowptr[MAXN + 1];
__device__ int   g_cursor[MAXN];
__device__ int   g_col[MAXE];
__device__ int   g_bsum[MAXB + 1];
__device__ int   g_cnti[MAXG];
__device__ float g_dinv[MAXN];
__device__ __align__(16) __nv_bfloat16 g_xb[(size_t)MAXN * 64];
__device__ __align__(16) __nv_bfloat16 g_hb[(size_t)MAXN * 128];
__device__ __align__(16) float g_t1[(size_t)MAXN * 64];
__device__ float g_pooled[MAXG * 128];

// ---------------- init: zero scratch (runs every replay) ---------------------
__global__ void init_kernel(int n, int g) {
    int i = blockIdx.x * blockDim.x + threadIdx.x;
    if (i < n) g_indeg[i] = 0;
    if (i < g * 128) g_pooled[i] = 0.0f;
    if (i < g) g_cnti[i] = 0;
}

// ------------- convert x -> bf16 (float4 granularity) + count degrees --------
__global__ void convert_count_kernel(const float* __restrict__ x,
                                     const int* __restrict__ ei,
                                     int nconv, int e) {
    int idx = blockIdx.x * blockDim.x + threadIdx.x;
    if (idx < nconv) {
        float4 v = ((const float4*)x)[idx];
        __nv_bfloat162 lo = __floats2bfloat162_rn(v.x, v.y);
        __nv_bfloat162 hi = __floats2bfloat162_rn(v.z, v.w);
        uint2 packed;
        packed.x = *reinterpret_cast<unsigned int*>(&lo);
        packed.y = *reinterpret_cast<unsigned int*>(&hi);
        ((uint2*)g_xb)[idx] = packed;
    }
    if (idx < e) atomicAdd(&g_indeg[ei[e + idx]], 1);
}

// ---------------- scan phase 1: per-block (4096 elems) exclusive scan --------
__global__ void __launch_bounds__(256) scan1_kernel(int n) {
    __shared__ int sh[4096];
    __shared__ int wsum[8];
    int t = threadIdx.x;
    int base = blockIdx.x * 4096;
#pragma unroll
    for (int j = 0; j < 16; j++) {
        int idx = base + t + j * 256;
        sh[t + j * 256] = (idx < n) ? g_indeg[idx] : 0;
    }
    __syncthreads();
    int v[16];
    int run = 0;
#pragma unroll
    for (int j = 0; j < 16; j++) { v[j] = run; run += sh[t * 16 + j]; }
    int lane = t & 31, w = t >> 5;
    int incl = run;
#pragma unroll
    for (int off = 1; off < 32; off <<= 1) {
        int tmp = __shfl_up_sync(0xffffffffu, incl, off);
        if (lane >= off) incl += tmp;
    }
    if (lane == 31) wsum[w] = incl;
    __syncthreads();
    if (t == 0) {
        int s = 0;
#pragma unroll
        for (int k = 0; k < 8; k++) { int x2 = wsum[k]; wsum[k] = s; s += x2; }
        g_bsum[blockIdx.x] = s;
    }
    __syncthreads();
    int texcl = wsum[w] + incl - run;
#pragma unroll
    for (int j = 0; j < 16; j++) sh[t * 16 + j] = texcl + v[j];
    __syncthreads();
#pragma unroll
    for (int j = 0; j < 16; j++) {
        int idx = base + t + j * 256;
        if (idx < n) g_rowptr[idx] = sh[t + j * 256];
    }
}

// ---------------- scan phase 2: scan block sums (1 warp) ----------------------
__global__ void scan2_kernel(int nb, int n) {
    int lane = threadIdx.x;
    int carry = 0;
    for (int base = 0; base < nb; base += 32) {
        int idx = base + lane;
        int x = (idx < nb) ? g_bsum[idx] : 0;
        int incl = x;
#pragma unroll
        for (int off = 1; off < 32; off <<= 1) {
            int tmp = __shfl_up_sync(0xffffffffu, incl, off);
            if (lane >= off) incl += tmp;
        }
        int excl = carry + incl - x;
        if (idx < nb) g_bsum[idx] = excl;
        carry += __shfl_sync(0xffffffffu, incl, 31);
    }
    if (lane == 0) g_rowptr[n] = carry;
}

// -------- scan phase 3: add block offsets + dinv + cursor + graph counts ------
__global__ void scan3_kernel(const int* __restrict__ batch, int n) {
    int i = blockIdx.x * blockDim.x + threadIdx.x;
    if (i < n) {
        int r = g_rowptr[i] + g_bsum[i >> 12];
        g_rowptr[i] = r;
        g_cursor[i] = r;
        g_dinv[i] = rsqrtf((float)(g_indeg[i] + 1));
        atomicAdd(&g_cnti[batch[i]], 1);
    }
}

// ---------------- scatter edges into CSR --------------------------------------
__global__ void scatter_kernel(const int* __restrict__ ei, int e) {
    int idx = blockIdx.x * blockDim.x + threadIdx.x;
    if (idx < e) {
        int s = ei[idx];
        int d = ei[e + idx];
        int pos = atomicAdd(&g_cursor[d], 1);
        g_col[pos] = s;
    }
}

// ---------------- agg1: t1 = A xb  (warp per node, bf16 gathers) --------------
__global__ void agg1_kernel(int n) {
    int warp = (blockIdx.x * blockDim.x + threadIdx.x) >> 5;
    int lane = threadIdx.x & 31;
    if (warp >= n) return;
    int i = warp;
    int p0 = g_rowptr[i], p1 = g_rowptr[i + 1];
    float2 acc = make_float2(0.f, 0.f);
    int p = p0;
    for (; p + 4 <= p1; p += 4) {
        int s0 = g_col[p], s1 = g_col[p + 1], s2 = g_col[p + 2], s3 = g_col[p + 3];
        float w0 = g_dinv[s0], w1 = g_dinv[s1], w2 = g_dinv[s2], w3 = g_dinv[s3];
        float2 v0 = __bfloat1622float2(*(const __nv_bfloat162*)(g_xb + (size_t)s0 * 64 + lane * 2));
        float2 v1 = __bfloat1622float2(*(const __nv_bfloat162*)(g_xb + (size_t)s1 * 64 + lane * 2));
        float2 v2 = __bfloat1622float2(*(const __nv_bfloat162*)(g_xb + (size_t)s2 * 64 + lane * 2));
        float2 v3 = __bfloat1622float2(*(const __nv_bfloat162*)(g_xb + (size_t)s3 * 64 + lane * 2));
        acc.x = fmaf(w0, v0.x, acc.x); acc.y = fmaf(w0, v0.y, acc.y);
        acc.x = fmaf(w1, v1.x, acc.x); acc.y = fmaf(w1, v1.y, acc.y);
        acc.x = fmaf(w2, v2.x, acc.x); acc.y = fmaf(w2, v2.y, acc.y);
        acc.x = fmaf(w3, v3.x, acc.x); acc.y = fmaf(w3, v3.y, acc.y);
    }
    for (; p < p1; ++p) {
        int s = g_col[p];
        float ws = g_dinv[s];
        float2 v = __bfloat1622float2(*(const __nv_bfloat162*)(g_xb + (size_t)s * 64 + lane * 2));
        acc.x = fmaf(ws, v.x, acc.x); acc.y = fmaf(ws, v.y, acc.y);
    }
    float di = g_dinv[i];
    float2 xi = __bfloat1622float2(*(const __nv_bfloat162*)(g_xb + (size_t)i * 64 + lane * 2));
    float2 r;
    r.x = di * acc.x + di * di * xi.x;
    r.y = di * acc.y + di * di * xi.y;
    *(float2*)(g_t1 + (size_t)i * 64 + lane * 2) = r;
}

// ---------------- GEMM: h = elu(t1 @ W1 + b1), f32x2 FFMA, bf16 out -----------
__global__ void __launch_bounds__(256) gemm1_kernel(const float* __restrict__ W1,
                                                    const float* __restrict__ b1,
                                                    int n) {
    __shared__ float As[64 * 64];
    __shared__ float Ws[64 * 128];
    int tid = threadIdx.x;
    int base = blockIdx.x * 64;

    const float4* Wv = (const float4*)W1;
    float4* Wsv = (float4*)Ws;
#pragma unroll
    for (int i = 0; i < 8; i++) Wsv[tid + i * 256] = Wv[tid + i * 256];

    const float4* Av = (const float4*)(g_t1 + (size_t)base * 64);
    float4* Asv = (float4*)As;
#pragma unroll
    for (int i = 0; i < 4; i++) {
        int idx = tid + i * 256;
        int row = base + (idx >> 4);
        float4 v = (row < n) ? Av[idx] : make_float4(0.f, 0.f, 0.f, 0.f);
        Asv[idx] = v;
    }
    __syncthreads();

    int tx = tid & 31, ty = tid >> 5;
    int c0 = tx * 4, r0 = ty * 8;
    unsigned long long accp[8][2];
#pragma unroll
    for (int r = 0; r < 8; r++) { accp[r][0] = 0ull; accp[r][1] = 0ull; }

#pragma unroll 4
    for (int k = 0; k < 64; k++) {
        ulonglong2 bb = *(const ulonglong2*)(Ws + k * 128 + c0);
#pragma unroll
        for (int r = 0; r < 8; r++) {
            unsigned int au = __float_as_uint(As[(r0 + r) * 64 + k]);
            unsigned long long ap;
            asm("mov.b64 %0, {%1, %1};" : "=l"(ap) : "r"(au));
            asm("fma.rn.f32x2 %0, %1, %2, %0;" : "+l"(accp[r][0]) : "l"(ap), "l"(bb.x));
            asm("fma.rn.f32x2 %0, %1, %2, %0;" : "+l"(accp[r][1]) : "l"(ap), "l"(bb.y));
        }
    }

    float4 bias = *(const float4*)&b1[c0];
#pragma unroll
    for (int r = 0; r < 8; r++) {
        int row = base + r0 + r;
        if (row < n) {
            unsigned int u0, u1, u2, u3;
            asm("mov.b64 {%0, %1}, %2;" : "=r"(u0), "=r"(u1) : "l"(accp[r][0]));
            asm("mov.b64 {%0, %1}, %2;" : "=r"(u2), "=r"(u3) : "l"(accp[r][1]));
            float4 o;
            o.x = __uint_as_float(u0) + bias.x;
            o.y = __uint_as_float(u1) + bias.y;
            o.z = __uint_as_float(u2) + bias.z;
            o.w = __uint_as_float(u3) + bias.w;
            o.x = (o.x > 0.f) ? o.x : expm1f(o.x);
            o.y = (o.y > 0.f) ? o.y : expm1f(o.y);
            o.z = (o.z > 0.f) ? o.z : expm1f(o.z);
            o.w = (o.w > 0.f) ? o.w : expm1f(o.w);
            __nv_bfloat162 lo = __floats2bfloat162_rn(o.x, o.y);
            __nv_bfloat162 hi = __floats2bfloat162_rn(o.z, o.w);
            uint2 packed;
            packed.x = *reinterpret_cast<unsigned int*>(&lo);
            packed.y = *reinterpret_cast<unsigned int*>(&hi);
            *(uint2*)(g_hb + (size_t)row * 128 + c0) = packed;
        }
    }
}

// -------- agg2 + mean-pool: pooled[g] += (A h)_i, bf16 gathers, unroll 8 ------
__device__ __forceinline__ float4 ld_h4(const __nv_bfloat16* p) {
    uint2 raw = *(const uint2*)p;
    __nv_bfloat162 b0 = *reinterpret_cast<__nv_bfloat162*>(&raw.x);
    __nv_bfloat162 b1 = *reinterpret_cast<__nv_bfloat162*>(&raw.y);
    float2 f0 = __bfloat1622float2(b0);
    float2 f1 = __bfloat1622float2(b1);
    return make_float4(f0.x, f0.y, f1.x, f1.y);
}

__global__ void __launch_bounds__(256) agg2_pool_kernel(const int* __restrict__ batch, int n) {
    __shared__ float ps[128];
    __shared__ int g0_s;
    int tid = threadIdx.x;
    int lane = tid & 31;
    int wid = tid >> 5;
    int node0 = blockIdx.x * 8;
    if (tid < 128) ps[tid] = 0.0f;
    if (tid == 0) g0_s = batch[node0 < n ? node0 : (n - 1)];
    __syncthreads();
    int g0 = g0_s;

    int i = node0 + wid;
    if (i < n) {
        int p0 = g_rowptr[i], p1 = g_rowptr[i + 1];
        float4 acc = make_float4(0.f, 0.f, 0.f, 0.f);
        int p = p0;
        for (; p + 8 <= p1; p += 8) {
            int s0 = g_col[p],     s1 = g_col[p + 1], s2 = g_col[p + 2], s3 = g_col[p + 3];
            int s4 = g_col[p + 4], s5 = g_col[p + 5], s6 = g_col[p + 6], s7 = g_col[p + 7];
            float w0 = g_dinv[s0], w1 = g_dinv[s1], w2 = g_dinv[s2], w3 = g_dinv[s3];
            float w4 = g_dinv[s4], w5 = g_dinv[s5], w6 = g_dinv[s6], w7 = g_dinv[s7];
            float4 v0 = ld_h4(g_hb + (size_t)s0 * 128 + lane * 4);
            float4 v1 = ld_h4(g_hb + (size_t)s1 * 128 + lane * 4);
            float4 v2 = ld_h4(g_hb + (size_t)s2 * 128 + lane * 4);
            float4 v3 = ld_h4(g_hb + (size_t)s3 * 128 + lane * 4);
            float4 v4 = ld_h4(g_hb + (size_t)s4 * 128 + lane * 4);
            float4 v5 = ld_h4(g_hb + (size_t)s5 * 128 + lane * 4);
            float4 v6 = ld_h4(g_hb + (size_t)s6 * 128 + lane * 4);
            float4 v7 = ld_h4(g_hb + (size_t)s7 * 128 + lane * 4);
            acc.x = fmaf(w0, v0.x, acc.x); acc.y = fmaf(w0, v0.y, acc.y);
            acc.z = fmaf(w0, v0.z, acc.z); acc.w = fmaf(w0, v0.w, acc.w);
            acc.x = fmaf(w1, v1.x, acc.x); acc.y = fmaf(w1, v1.y, acc.y);
            acc.z = fmaf(w1, v1.z, acc.z); acc.w = fmaf(w1, v1.w, acc.w);
            acc.x = fmaf(w2, v2.x, acc.x); acc.y = fmaf(w2, v2.y, acc.y);
            acc.z = fmaf(w2, v2.z, acc.z); acc.w = fmaf(w2, v2.w, acc.w);
            acc.x = fmaf(w3, v3.x, acc.x); acc.y = fmaf(w3, v3.y, acc.y);
            acc.z = fmaf(w3, v3.z, acc.z); acc.w = fmaf(w3, v3.w, acc.w);
            acc.x = fmaf(w4, v4.x, acc.x); acc.y = fmaf(w4, v4.y, acc.y);
            acc.z = fmaf(w4, v4.z, acc.z); acc.w = fmaf(w4, v4.w, acc.w);
            acc.x = fmaf(w5, v5.x, acc.x); acc.y = fmaf(w5, v5.y, acc.y);
            acc.z = fmaf(w5, v5.z, acc.z); acc.w = fmaf(w5, v5.w, acc.w);
            acc.x = fmaf(w6, v6.x, acc.x); acc.y = fmaf(w6, v6.y, acc.y);
            acc.z = fmaf(w6, v6.z, acc.z); acc.w = fmaf(w6, v6.w, acc.w);
            acc.x = fmaf(w7, v7.x, acc.x); acc.y = fmaf(w7, v7.y, acc.y);
            acc.z = fmaf(w7, v7.z, acc.z); acc.w = fmaf(w7, v7.w, acc.w);
        }
        for (; p < p1; ++p) {
            int s = g_col[p];
            float w = g_dinv[s];
            float4 v = ld_h4(g_hb + (size_t)s * 128 + lane * 4);
            acc.x = fmaf(w, v.x, acc.x); acc.y = fmaf(w, v.y, acc.y);
            acc.z = fmaf(w, v.z, acc.z); acc.w = fmaf(w, v.w, acc.w);
        }
        float di = g_dinv[i];
        float4 hi = ld_h4(g_hb + (size_t)i * 128 + lane * 4);
        float4 r;
        r.x = di * acc.x + di * di * hi.x;
        r.y = di * acc.y + di * di * hi.y;
        r.z = di * acc.z + di * di * hi.z;
        r.w = di * acc.w + di * di * hi.w;
        int g = batch[i];
        if (g == g0) {
            atomicAdd(&ps[lane * 4 + 0], r.x);
            atomicAdd(&ps[lane * 4 + 1], r.y);
            atomicAdd(&ps[lane * 4 + 2], r.z);
            atomicAdd(&ps[lane * 4 + 3], r.w);
        } else {
            float* pg = g_pooled + g * 128 + lane * 4;
            atomicAdd(pg + 0, r.x);
            atomicAdd(pg + 1, r.y);
            atomicAdd(pg + 2, r.z);
            atomicAdd(pg + 3, r.w);
        }
    }
    __syncthreads();
    if (tid < 128) atomicAdd(&g_pooled[g0 * 128 + tid], ps[tid]);
}

// ---------------- epilogue: W2 + MLP + log_softmax (1 block per graph) --------
__global__ void __launch_bounds__(128) final_kernel(
    const float* __restrict__ stats,
    const float* __restrict__ W2, const float* __restrict__ b2,
    const float* __restrict__ Wf1, const float* __restrict__ bf1,
    const float* __restrict__ Wf2, const float* __restrict__ bf2,
    float* __restrict__ out) {
    __shared__ float pm[128];
    __shared__ float zin[138];
    __shared__ float z1[20];
    __shared__ float z2[5];
    int g = blockIdx.x, t = threadIdx.x;
    float c = fmaxf((float)g_cnti[g], 1.0f);
    pm[t] = g_pooled[g * 128 + t] / c;
    __syncthreads();
    float acc = b2[t];
#pragma unroll 8
    for (int k = 0; k < 128; k++) acc = fmaf(pm[k], W2[k * 128 + t], acc);
    zin[t] = acc;
    if (t < 10) zin[128 + t] = stats[g * 10 + t];
    __syncthreads();
    if (t < 20) {
        float a = bf1[t];
        for (int k = 0; k < 138; k++) a = fmaf(zin[k], Wf1[k * 20 + t], a);
        z1[t] = fmaxf(a, 0.0f);
    }
    __syncthreads();
    if (t < 5) {
        float a = bf2[t];
        for (int k = 0; k < 20; k++) a = fmaf(z1[k], Wf2[k * 5 + t], a);
        z2[t] = a;
    }
    __syncthreads();
    if (t == 0) {
        float m = z2[0];
        for (int i = 1; i < 5; i++) m = fmaxf(m, z2[i]);
        float sum = 0.0f;
        for (int i = 0; i < 5; i++) sum += expf(z2[i] - m);
        float ls = m + logf(sum);
        for (int i = 0; i < 5; i++) out[g * 5 + i] = z2[i] - ls;
    }
}

// ---------------------------------------------------------------------------
extern "C" void kernel_launch(void* const* d_in, const int* in_sizes, int n_in,
                              void* d_out, int out_size) {
    const float* x     = (const float*)d_in[0];
    const int*   ei    = (const int*)d_in[1];
    const int*   batch = (const int*)d_in[2];
    const float* stats = (const float*)d_in[4];
    const float* W1    = (const float*)d_in[5];
    const float* b1    = (const float*)d_in[6];
    const float* W2    = (const float*)d_in[7];
    const float* b2    = (const float*)d_in[8];
    const float* Wf1   = (const float*)d_in[9];
    const float* bf1   = (const float*)d_in[10];
    const float* Wf2   = (const float*)d_in[11];
    const float* bf2   = (const float*)d_in[12];

    int n = in_sizes[0] / 64;
    int e = in_sizes[1] / 2;
    int G = in_sizes[4] / 10;
    int nb = (n + 4095) / 4096;
    int nconv = n * 16;
    int big = (nconv > e) ? nconv : e;

    init_kernel<<<(n + 255) / 256, 256>>>(n, G);
    convert_count_kernel<<<(big + 255) / 256, 256>>>(x, ei, nconv, e);
    scan1_kernel<<<nb, 256>>>(n);
    scan2_kernel<<<1, 32>>>(nb, n);
    scan3_kernel<<<(n + 255) / 256, 256>>>(batch, n);
    scatter_kernel<<<(e + 255) / 256, 256>>>(ei, e);
    agg1_kernel<<<(n * 32 + 255) / 256, 256>>>(n);
    gemm1_kernel<<<(n + 63) / 64, 256>>>(W1, b1, n);
    agg2_pool_kernel<<<(n + 7) / 8, 256>>>(batch, n);
    final_kernel<<<G, 128>>>(stats, W2, b2, Wf1, bf1, Wf2, bf2, (float*)d_out);
}

// round 7
// speedup vs baseline: 1.1097x; 1.0014x over previous
#include <cuda_runtime.h>
#include <cuda_bf16.h>
#include <math.h>

// ---------------------------------------------------------------------------
// GCN forward with dinv pre-scaled payloads:
//   xb'_s = bf16(dinv[s] * x_s)          (convert after dinv known)
//   t1_i  = dinv[i] * (sum_nbr xb'_s + xb'_i)
//   h     = elu(t1 @ W1 + b1);  hb'_i = bf16(dinv[i] * h_i)
//   (A h)_i = dinv[i] * (sum_nbr hb'_s + hb'_i)  -> pooled[batch[i]]
//   epilogue: mean, W2, concat stats, MLP, log_softmax
// Per-edge inner loop: load col, load payload. No weight load.
// ---------------------------------------------------------------------------

#define MAXN 100000
#define MAXE 1600000
#define MAXG 64
#define MAXB ((MAXN + 4095) / 4096)

__device__ int   g_indeg[MAXN];
__device__ int   g_rowptr[MAXN + 1];
__device__ int   g_cursor[MAXN];
__device__ int   g_col[MAXE];
__device__ int   g_bsum[MAXB + 1];
__device__ int   g_cnti[MAXG];
__device__ float g_dinv[MAXN];
__device__ __align__(16) __nv_bfloat16 g_xb[(size_t)MAXN * 64];
__device__ __align__(16) __nv_bfloat16 g_hb[(size_t)MAXN * 128];
__device__ __align__(16) float g_t1[(size_t)MAXN * 64];
__device__ float g_pooled[MAXG * 128];

// ---------------- init: zero scratch (runs every replay) ---------------------
__global__ void init_kernel(int n, int g) {
    int i = blockIdx.x * blockDim.x + threadIdx.x;
    if (i < n) g_indeg[i] = 0;
    if (i < g * 128) g_pooled[i] = 0.0f;
    if (i < g) g_cnti[i] = 0;
}

// ---------------- count in-degree ---------------------------------------------
__global__ void count_kernel(const int* __restrict__ ei, int e) {
    int idx = blockIdx.x * blockDim.x + threadIdx.x;
    if (idx < e) atomicAdd(&g_indeg[ei[e + idx]], 1);
}

// ---------------- scan phase 1: per-block (4096 elems) exclusive scan --------
__global__ void __launch_bounds__(256) scan1_kernel(int n) {
    __shared__ int sh[4096];
    __shared__ int wsum[8];
    int t = threadIdx.x;
    int base = blockIdx.x * 4096;
#pragma unroll
    for (int j = 0; j < 16; j++) {
        int idx = base + t + j * 256;
        sh[t + j * 256] = (idx < n) ? g_indeg[idx] : 0;
    }
    __syncthreads();
    int v[16];
    int run = 0;
#pragma unroll
    for (int j = 0; j < 16; j++) { v[j] = run; run += sh[t * 16 + j]; }
    int lane = t & 31, w = t >> 5;
    int incl = run;
#pragma unroll
    for (int off = 1; off < 32; off <<= 1) {
        int tmp = __shfl_up_sync(0xffffffffu, incl, off);
        if (lane >= off) incl += tmp;
    }
    if (lane == 31) wsum[w] = incl;
    __syncthreads();
    if (t == 0) {
        int s = 0;
#pragma unroll
        for (int k = 0; k < 8; k++) { int x2 = wsum[k]; wsum[k] = s; s += x2; }
        g_bsum[blockIdx.x] = s;
    }
    __syncthreads();
    int texcl = wsum[w] + incl - run;
#pragma unroll
    for (int j = 0; j < 16; j++) sh[t * 16 + j] = texcl + v[j];
    __syncthreads();
#pragma unroll
    for (int j = 0; j < 16; j++) {
        int idx = base + t + j * 256;
        if (idx < n) g_rowptr[idx] = sh[t + j * 256];
    }
}

// ---------------- scan phase 2: scan block sums (1 warp) ----------------------
__global__ void scan2_kernel(int nb, int n) {
    int lane = threadIdx.x;
    int carry = 0;
    for (int base = 0; base < nb; base += 32) {
        int idx = base + lane;
        int x = (idx < nb) ? g_bsum[idx] : 0;
        int incl = x;
#pragma unroll
        for (int off = 1; off < 32; off <<= 1) {
            int tmp = __shfl_up_sync(0xffffffffu, incl, off);
            if (lane >= off) incl += tmp;
        }
        int excl = carry + incl - x;
        if (idx < nb) g_bsum[idx] = excl;
        carry += __shfl_sync(0xffffffffu, incl, 31);
    }
    if (lane == 0) g_rowptr[n] = carry;
}

// -------- scan phase 3: block offsets + dinv + cursor + graph counts ----------
__global__ void scan3_kernel(const int* __restrict__ batch, int n) {
    int i = blockIdx.x * blockDim.x + threadIdx.x;
    if (i < n) {
        int r = g_rowptr[i] + g_bsum[i >> 12];
        g_rowptr[i] = r;
        g_cursor[i] = r;
        g_dinv[i] = rsqrtf((float)(g_indeg[i] + 1));
        atomicAdd(&g_cnti[batch[i]], 1);
    }
}

// ------------- convert: xb' = bf16(dinv[node] * x)  (float4 granularity) ------
__global__ void convert_kernel(const float* __restrict__ x, int nconv) {
    int idx = blockIdx.x * blockDim.x + threadIdx.x;
    if (idx < nconv) {
        float d = g_dinv[idx >> 4];
        float4 v = ((const float4*)x)[idx];
        __nv_bfloat162 lo = __floats2bfloat162_rn(d * v.x, d * v.y);
        __nv_bfloat162 hi = __floats2bfloat162_rn(d * v.z, d * v.w);
        uint2 packed;
        packed.x = *reinterpret_cast<unsigned int*>(&lo);
        packed.y = *reinterpret_cast<unsigned int*>(&hi);
        ((uint2*)g_xb)[idx] = packed;
    }
}

// ---------------- scatter edges into CSR --------------------------------------
__global__ void scatter_kernel(const int* __restrict__ ei, int e) {
    int idx = blockIdx.x * blockDim.x + threadIdx.x;
    if (idx < e) {
        int s = ei[idx];
        int d = ei[e + idx];
        int pos = atomicAdd(&g_cursor[d], 1);
        g_col[pos] = s;
    }
}

// ---------------- agg1: t1_i = di*(sum xb'_s + xb'_i)  (warp per node) --------
__global__ void agg1_kernel(int n) {
    int warp = (blockIdx.x * blockDim.x + threadIdx.x) >> 5;
    int lane = threadIdx.x & 31;
    if (warp >= n) return;
    int i = warp;
    int p0 = g_rowptr[i], p1 = g_rowptr[i + 1];
    float2 acc = make_float2(0.f, 0.f);
    int p = p0;
    for (; p + 8 <= p1; p += 8) {
        int s0 = g_col[p],     s1 = g_col[p + 1], s2 = g_col[p + 2], s3 = g_col[p + 3];
        int s4 = g_col[p + 4], s5 = g_col[p + 5], s6 = g_col[p + 6], s7 = g_col[p + 7];
        float2 v0 = __bfloat1622float2(*(const __nv_bfloat162*)(g_xb + (size_t)s0 * 64 + lane * 2));
        float2 v1 = __bfloat1622float2(*(const __nv_bfloat162*)(g_xb + (size_t)s1 * 64 + lane * 2));
        float2 v2 = __bfloat1622float2(*(const __nv_bfloat162*)(g_xb + (size_t)s2 * 64 + lane * 2));
        float2 v3 = __bfloat1622float2(*(const __nv_bfloat162*)(g_xb + (size_t)s3 * 64 + lane * 2));
        float2 v4 = __bfloat1622float2(*(const __nv_bfloat162*)(g_xb + (size_t)s4 * 64 + lane * 2));
        float2 v5 = __bfloat1622float2(*(const __nv_bfloat162*)(g_xb + (size_t)s5 * 64 + lane * 2));
        float2 v6 = __bfloat1622float2(*(const __nv_bfloat162*)(g_xb + (size_t)s6 * 64 + lane * 2));
        float2 v7 = __bfloat1622float2(*(const __nv_bfloat162*)(g_xb + (size_t)s7 * 64 + lane * 2));
        acc.x += v0.x + v1.x + v2.x + v3.x + v4.x + v5.x + v6.x + v7.x;
        acc.y += v0.y + v1.y + v2.y + v3.y + v4.y + v5.y + v6.y + v7.y;
    }
    for (; p < p1; ++p) {
        int s = g_col[p];
        float2 v = __bfloat1622float2(*(const __nv_bfloat162*)(g_xb + (size_t)s * 64 + lane * 2));
        acc.x += v.x; acc.y += v.y;
    }
    float di = g_dinv[i];
    float2 xi = __bfloat1622float2(*(const __nv_bfloat162*)(g_xb + (size_t)i * 64 + lane * 2));
    float2 r;
    r.x = di * (acc.x + xi.x);
    r.y = di * (acc.y + xi.y);
    *(float2*)(g_t1 + (size_t)i * 64 + lane * 2) = r;
}

// -------- GEMM: h = elu(t1 @ W1 + b1); store hb' = bf16(dinv*h) ---------------
__global__ void __launch_bounds__(256) gemm1_kernel(const float* __restrict__ W1,
                                                    const float* __restrict__ b1,
                                                    int n) {
    __shared__ float As[64 * 64];
    __shared__ float Ws[64 * 128];
    int tid = threadIdx.x;
    int base = blockIdx.x * 64;

    const float4* Wv = (const float4*)W1;
    float4* Wsv = (float4*)Ws;
#pragma unroll
    for (int i = 0; i < 8; i++) Wsv[tid + i * 256] = Wv[tid + i * 256];

    const float4* Av = (const float4*)(g_t1 + (size_t)base * 64);
    float4* Asv = (float4*)As;
#pragma unroll
    for (int i = 0; i < 4; i++) {
        int idx = tid + i * 256;
        int row = base + (idx >> 4);
        float4 v = (row < n) ? Av[idx] : make_float4(0.f, 0.f, 0.f, 0.f);
        Asv[idx] = v;
    }
    __syncthreads();

    int tx = tid & 31, ty = tid >> 5;
    int c0 = tx * 4, r0 = ty * 8;
    unsigned long long accp[8][2];
#pragma unroll
    for (int r = 0; r < 8; r++) { accp[r][0] = 0ull; accp[r][1] = 0ull; }

#pragma unroll 4
    for (int k = 0; k < 64; k++) {
        ulonglong2 bb = *(const ulonglong2*)(Ws + k * 128 + c0);
#pragma unroll
        for (int r = 0; r < 8; r++) {
            unsigned int au = __float_as_uint(As[(r0 + r) * 64 + k]);
            unsigned long long ap;
            asm("mov.b64 %0, {%1, %1};" : "=l"(ap) : "r"(au));
            asm("fma.rn.f32x2 %0, %1, %2, %0;" : "+l"(accp[r][0]) : "l"(ap), "l"(bb.x));
            asm("fma.rn.f32x2 %0, %1, %2, %0;" : "+l"(accp[r][1]) : "l"(ap), "l"(bb.y));
        }
    }

    float4 bias = *(const float4*)&b1[c0];
#pragma unroll
    for (int r = 0; r < 8; r++) {
        int row = base + r0 + r;
        if (row < n) {
            float di = g_dinv[row];
            unsigned int u0, u1, u2, u3;
            asm("mov.b64 {%0, %1}, %2;" : "=r"(u0), "=r"(u1) : "l"(accp[r][0]));
            asm("mov.b64 {%0, %1}, %2;" : "=r"(u2), "=r"(u3) : "l"(accp[r][1]));
            float4 o;
            o.x = __uint_as_float(u0) + bias.x;
            o.y = __uint_as_float(u1) + bias.y;
            o.z = __uint_as_float(u2) + bias.z;
            o.w = __uint_as_float(u3) + bias.w;
            o.x = (o.x > 0.f) ? o.x : expm1f(o.x);
            o.y = (o.y > 0.f) ? o.y : expm1f(o.y);
            o.z = (o.z > 0.f) ? o.z : expm1f(o.z);
            o.w = (o.w > 0.f) ? o.w : expm1f(o.w);
            __nv_bfloat162 lo = __floats2bfloat162_rn(di * o.x, di * o.y);
            __nv_bfloat162 hi = __floats2bfloat162_rn(di * o.z, di * o.w);
            uint2 packed;
            packed.x = *reinterpret_cast<unsigned int*>(&lo);
            packed.y = *reinterpret_cast<unsigned int*>(&hi);
            *(uint2*)(g_hb + (size_t)row * 128 + c0) = packed;
        }
    }
}

// -------- agg2 + mean-pool: pooled[g] += di*(sum hb'_s + hb'_i) ---------------
__device__ __forceinline__ float4 ld_h4(const __nv_bfloat16* p) {
    uint2 raw = *(const uint2*)p;
    __nv_bfloat162 b0 = *reinterpret_cast<__nv_bfloat162*>(&raw.x);
    __nv_bfloat162 b1 = *reinterpret_cast<__nv_bfloat162*>(&raw.y);
    float2 f0 = __bfloat1622float2(b0);
    float2 f1 = __bfloat1622float2(b1);
    return make_float4(f0.x, f0.y, f1.x, f1.y);
}

__global__ void __launch_bounds__(256) agg2_pool_kernel(const int* __restrict__ batch, int n) {
    __shared__ float ps[128];
    __shared__ int g0_s;
    int tid = threadIdx.x;
    int lane = tid & 31;
    int wid = tid >> 5;
    int node0 = blockIdx.x * 8;
    if (tid < 128) ps[tid] = 0.0f;
    if (tid == 0) g0_s = batch[node0 < n ? node0 : (n - 1)];
    __syncthreads();
    int g0 = g0_s;

    int i = node0 + wid;
    if (i < n) {
        int p0 = g_rowptr[i], p1 = g_rowptr[i + 1];
        float4 acc = make_float4(0.f, 0.f, 0.f, 0.f);
        int p = p0;
        for (; p + 8 <= p1; p += 8) {
            int s0 = g_col[p],     s1 = g_col[p + 1], s2 = g_col[p + 2], s3 = g_col[p + 3];
            int s4 = g_col[p + 4], s5 = g_col[p + 5], s6 = g_col[p + 6], s7 = g_col[p + 7];
            float4 v0 = ld_h4(g_hb + (size_t)s0 * 128 + lane * 4);
            float4 v1 = ld_h4(g_hb + (size_t)s1 * 128 + lane * 4);
            float4 v2 = ld_h4(g_hb + (size_t)s2 * 128 + lane * 4);
            float4 v3 = ld_h4(g_hb + (size_t)s3 * 128 + lane * 4);
            float4 v4 = ld_h4(g_hb + (size_t)s4 * 128 + lane * 4);
            float4 v5 = ld_h4(g_hb + (size_t)s5 * 128 + lane * 4);
            float4 v6 = ld_h4(g_hb + (size_t)s6 * 128 + lane * 4);
            float4 v7 = ld_h4(g_hb + (size_t)s7 * 128 + lane * 4);
            acc.x += v0.x + v1.x + v2.x + v3.x + v4.x + v5.x + v6.x + v7.x;
            acc.y += v0.y + v1.y + v2.y + v3.y + v4.y + v5.y + v6.y + v7.y;
            acc.z += v0.z + v1.z + v2.z + v3.z + v4.z + v5.z + v6.z + v7.z;
            acc.w += v0.w + v1.w + v2.w + v3.w + v4.w + v5.w + v6.w + v7.w;
        }
        for (; p < p1; ++p) {
            int s = g_col[p];
            float4 v = ld_h4(g_hb + (size_t)s * 128 + lane * 4);
            acc.x += v.x; acc.y += v.y; acc.z += v.z; acc.w += v.w;
        }
        float di = g_dinv[i];
        float4 hi = ld_h4(g_hb + (size_t)i * 128 + lane * 4);
        float4 r;
        r.x = di * (acc.x + hi.x);
        r.y = di * (acc.y + hi.y);
        r.z = di * (acc.z + hi.z);
        r.w = di * (acc.w + hi.w);
        int g = batch[i];
        if (g == g0) {
            atomicAdd(&ps[lane * 4 + 0], r.x);
            atomicAdd(&ps[lane * 4 + 1], r.y);
            atomicAdd(&ps[lane * 4 + 2], r.z);
            atomicAdd(&ps[lane * 4 + 3], r.w);
        } else {
            float* pg = g_pooled + g * 128 + lane * 4;
            atomicAdd(pg + 0, r.x);
            atomicAdd(pg + 1, r.y);
            atomicAdd(pg + 2, r.z);
            atomicAdd(pg + 3, r.w);
        }
    }
    __syncthreads();
    if (tid < 128) atomicAdd(&g_pooled[g0 * 128 + tid], ps[tid]);
}

// ---------------- epilogue: W2 + MLP + log_softmax (1 block per graph) --------
__global__ void __launch_bounds__(128) final_kernel(
    const float* __restrict__ stats,
    const float* __restrict__ W2, const float* __restrict__ b2,
    const float* __restrict__ Wf1, const float* __restrict__ bf1,
    const float* __restrict__ Wf2, const float* __restrict__ bf2,
    float* __restrict__ out) {
    __shared__ float pm[128];
    __shared__ float zin[138];
    __shared__ float z1[20];
    __shared__ float z2[5];
    int g = blockIdx.x, t = threadIdx.x;
    float c = fmaxf((float)g_cnti[g], 1.0f);
    pm[t] = g_pooled[g * 128 + t] / c;
    __syncthreads();
    float acc = b2[t];
#pragma unroll 8
    for (int k = 0; k < 128; k++) acc = fmaf(pm[k], W2[k * 128 + t], acc);
    zin[t] = acc;
    if (t < 10) zin[128 + t] = stats[g * 10 + t];
    __syncthreads();
    if (t < 20) {
        float a = bf1[t];
        for (int k = 0; k < 138; k++) a = fmaf(zin[k], Wf1[k * 20 + t], a);
        z1[t] = fmaxf(a, 0.0f);
    }
    __syncthreads();
    if (t < 5) {
        float a = bf2[t];
        for (int k = 0; k < 20; k++) a = fmaf(z1[k], Wf2[k * 5 + t], a);
        z2[t] = a;
    }
    __syncthreads();
    if (t == 0) {
        float m = z2[0];
        for (int i = 1; i < 5; i++) m = fmaxf(m, z2[i]);
        float sum = 0.0f;
        for (int i = 0; i < 5; i++) sum += expf(z2[i] - m);
        float ls = m + logf(sum);
        for (int i = 0; i < 5; i++) out[g * 5 + i] = z2[i] - ls;
    }
}

// ---------------------------------------------------------------------------
extern "C" void kernel_launch(void* const* d_in, const int* in_sizes, int n_in,
                              void* d_out, int out_size) {
    const float* x     = (const float*)d_in[0];
    const int*   ei    = (const int*)d_in[1];
    const int*   batch = (const int*)d_in[2];
    const float* stats = (const float*)d_in[4];
    const float* W1    = (const float*)d_in[5];
    const float* b1    = (const float*)d_in[6];
    const float* W2    = (const float*)d_in[7];
    const float* b2    = (const float*)d_in[8];
    const float* Wf1   = (const float*)d_in[9];
    const float* bf1   = (const float*)d_in[10];
    const float* Wf2   = (const float*)d_in[11];
    const float* bf2   = (const float*)d_in[12];

    int n = in_sizes[0] / 64;
    int e = in_sizes[1] / 2;
    int G = in_sizes[4] / 10;
    int nb = (n + 4095) / 4096;
    int nconv = n * 16;

    init_kernel<<<(n + 255) / 256, 256>>>(n, G);
    count_kernel<<<(e + 255) / 256, 256>>>(ei, e);
    scan1_kernel<<<nb, 256>>>(n);
    scan2_kernel<<<1, 32>>>(nb, n);
    scan3_kernel<<<(n + 255) / 256, 256>>>(batch, n);
    convert_kernel<<<(nconv + 255) / 256, 256>>>(x, nconv);
    scatter_kernel<<<(e + 255) / 256, 256>>>(ei, e);
    agg1_kernel<<<(n * 32 + 255) / 256, 256>>>(n);
    gemm1_kernel<<<(n + 63) / 64, 256>>>(W1, b1, n);
    agg2_pool_kernel<<<(n + 7) / 8, 256>>>(batch, n);
    final_kernel<<<G, 128>>>(stats, W2, b2, Wf1, bf1, Wf2, bf2, (float*)d_out);
}